// round 1
// baseline (speedup 1.0000x reference)
#include <cuda_runtime.h>

// FocalLoss_53541062312426 — GB300 sm_103a
// Inputs:  d_in[0] classifications [256,16384,2] f32
//          d_in[1] regressions     [256,16384,1] f32
//          d_in[2] annotations     [256,3,16384] f32 (beat, downbeat, beat_times)
// Output:  d_out [2] f32 = (mean cls_loss, mean reg_loss)

namespace {
constexpr int   B_       = 256;
constexpr int   T_       = 16384;
constexpr int   CHUNKS   = 8;
constexpr int   TCHUNK   = T_ / CHUNKS;     // 2048
constexpr int   NTHREADS = 256;
constexpr int   TPT      = TCHUNK / NTHREADS; // 8
constexpr float EPS_     = 1e-4f;
constexpr float LN2F     = 0.6931471805599453f;
// rn = ann2 / (T * 256 / 22050)
constexpr float INV_C    = 22050.0f / (16384.0f * 256.0f);
}

// per-(sample,chunk) partials: [cls_sum(lg2 units), num_pos, reg_sum, K]
__device__ float g_part[B_ * CHUNKS * 4];

__device__ __forceinline__ float focal_term(float c, bool lab) {
    c = fminf(fmaxf(c, EPS_), 1.0f - EPS_);
    float omc = 1.0f - c;
    float p = lab ? c : omc;      // prob of the true side
    float q = lab ? omc : c;      // (1 - p)
    float a = lab ? 0.25f : 0.75f;
    float q2 = q * q;
    float q5 = q2 * q2 * q;       // (1-p)^5
    // contribution in lg2 units; scaled by ln2 once at partial write
    return a * q5 * (-__log2f(p));
}

__global__ void __launch_bounds__(NTHREADS)
loss_main(const float* __restrict__ cls,
          const float* __restrict__ reg,
          const float* __restrict__ ann)
{
    const int bidx  = blockIdx.x;
    const int b     = bidx >> 3;       // / CHUNKS
    const int chunk = bidx & (CHUNKS - 1);
    const int t0    = chunk * TCHUNK + threadIdx.x * TPT;

    const float* __restrict__ ann0 = ann + (size_t)b * 3 * T_;
    const float* __restrict__ ann1 = ann0 + T_;
    const float* __restrict__ ann2 = ann0 + 2 * T_;
    const float* __restrict__ clsb = cls + (size_t)b * T_ * 2;
    const float* __restrict__ regb = reg + (size_t)b * T_;

    float cacc = 0.0f;   // focal loss partial (lg2 units)
    float npos = 0.0f;   // original beat count
    float racc = 0.0f;   // regression partial
    float kacc = 0.0f;   // valid (adjusted-beat) count

#pragma unroll
    for (int g = 0; g < TPT / 4; ++g) {
        const int tg = t0 + 4 * g;
        const float4 bv  = *reinterpret_cast<const float4*>(ann0 + tg);
        const float4 dv  = *reinterpret_cast<const float4*>(ann1 + tg);
        const float4 c01 = *reinterpret_cast<const float4*>(clsb + 2 * tg);
        const float4 c23 = *reinterpret_cast<const float4*>(clsb + 2 * tg + 4);

        const float bt[4] = {bv.x, bv.y, bv.z, bv.w};
        const float dn[4] = {dv.x, dv.y, dv.z, dv.w};
        const float cc[8] = {c01.x, c01.y, c01.z, c01.w,
                             c23.x, c23.y, c23.z, c23.w};

#pragma unroll
        for (int j = 0; j < 4; ++j) {
            const int   t    = tg + j;
            const float beat = bt[j];
            const bool  isb  = (beat != 0.0f);
            const bool  isd  = (dn[j] != 0.0f);

            cacc += focal_term(cc[2 * j],     isb &&  isd);  // class 0: downbeat
            cacc += focal_term(cc[2 * j + 1], isb && !isd);  // class 1: other beat
            npos += beat;

            // regression anchor mask with last-frame adjustment:
            //   pos[T-2] |= beat[T-1] ;  pos[T-1] = 0
            float posf = beat;
            if (t >= T_ - 2) {
                const float lastb = ann0[T_ - 1];
                if (t == T_ - 2) {
                    if (lastb != 0.0f) posf = 1.0f;
                } else {           // t == T_-1
                    posf = 0.0f;
                }
            }
            if (posf != 0.0f) {
                const float rn = ann2[t] * INV_C;
                const float r0 = regb[t];
                const float r1 = regb[t + 1];   // t <= T-2 guaranteed here
                const float d0 = rn - r0;
                const float d1 = rn - r1;
                racc += 0.5f * (d0 * d0 + d1 * d1);
                kacc += 1.0f;
            }
        }
    }

    // ---- block reduction of 4 accumulators ----
    const unsigned lane = threadIdx.x & 31u;
    const unsigned wid  = threadIdx.x >> 5;
#pragma unroll
    for (int o = 16; o > 0; o >>= 1) {
        cacc += __shfl_down_sync(0xffffffffu, cacc, o);
        npos += __shfl_down_sync(0xffffffffu, npos, o);
        racc += __shfl_down_sync(0xffffffffu, racc, o);
        kacc += __shfl_down_sync(0xffffffffu, kacc, o);
    }
    __shared__ float sm[NTHREADS / 32][4];
    if (lane == 0) {
        sm[wid][0] = cacc; sm[wid][1] = npos;
        sm[wid][2] = racc; sm[wid][3] = kacc;
    }
    __syncthreads();
    if (threadIdx.x == 0) {
        float c = 0.0f, n = 0.0f, r = 0.0f, k = 0.0f;
#pragma unroll
        for (int w = 0; w < NTHREADS / 32; ++w) {
            c += sm[w][0]; n += sm[w][1]; r += sm[w][2]; k += sm[w][3];
        }
        float* o = &g_part[bidx * 4];
        o[0] = c * LN2F;   // convert lg2 accumulation -> natural log
        o[1] = n;
        o[2] = r;
        o[3] = k;
    }
}

__global__ void __launch_bounds__(256)
loss_final(float* __restrict__ out)
{
    const int b = threadIdx.x;   // one thread per sample
    float cs = 0.0f, np = 0.0f, rs = 0.0f, kk = 0.0f;
#pragma unroll
    for (int ch = 0; ch < CHUNKS; ++ch) {
        const float* p = &g_part[(b * CHUNKS + ch) * 4];
        cs += p[0]; np += p[1]; rs += p[2]; kk += p[3];
    }
    float cl = cs / np * 10.0f;
    float rl = rs / kk * 10.0f;

    const unsigned lane = threadIdx.x & 31u;
    const unsigned wid  = threadIdx.x >> 5;
#pragma unroll
    for (int o = 16; o > 0; o >>= 1) {
        cl += __shfl_down_sync(0xffffffffu, cl, o);
        rl += __shfl_down_sync(0xffffffffu, rl, o);
    }
    __shared__ float sc[8], sr[8];
    if (lane == 0) { sc[wid] = cl; sr[wid] = rl; }
    __syncthreads();
    if (threadIdx.x == 0) {
        float a = 0.0f, r = 0.0f;
#pragma unroll
        for (int w = 0; w < 8; ++w) { a += sc[w]; r += sr[w]; }
        out[0] = a * (1.0f / 256.0f);
        out[1] = r * (1.0f / 256.0f);
    }
}

extern "C" void kernel_launch(void* const* d_in, const int* in_sizes, int n_in,
                              void* d_out, int out_size) {
    const float* cls = (const float*)d_in[0];
    const float* reg = (const float*)d_in[1];
    const float* ann = (const float*)d_in[2];
    float* out = (float*)d_out;
    (void)in_sizes; (void)n_in; (void)out_size;

    loss_main<<<B_ * CHUNKS, NTHREADS>>>(cls, reg, ann);
    loss_final<<<1, 256>>>(out);
}